// round 17
// baseline (speedup 1.0000x reference)
#include <cuda_runtime.h>
#include <cuda_fp16.h>
#include <cstdint>
#include <cstddef>

// Problem constants
#define BB    64
#define VV    32000
#define EE    512
#define HH    1024
#define G3    3072
#define TT    64
#define DINIT 768
#define DATT  256

// HMMA tiling
#define KCH   32           // K-chunk
#define NKC   (HH / KCH)   // 32 chunks (logits / gh)
#define NKS   (HH / 16)    // 64 k16-steps (logits / gh)
#define NG    (VV / 8)     // 4000 n8-groups (logits)
#define NGG   (G3 / 8)     // 384 n8-groups (gates)
#define WP    40           // SMEM row pitch in fp16 (80B, conflict-free LDSM)

// logits cp.async pipeline
#define NSTG  4                        // stages
#define STG_U4 1024                    // uint4 per stage (16KB)
#define SB_BYTES (NSTG * STG_U4 * 16)  // 65536
#define SH_BYTES (64 * WP * 2)         // 5120 per level
#define DYN_TOTAL (SB_BYTES + 2 * SH_BYTES)

// ---------------- scratch (device globals; no allocations allowed) ----------
__device__ float g_h[BB * HH];                 // hidden state (in-place update)
__device__ float g_gi[BB * G3];                // x @ W_ih^T + b_ih
__device__ float g_gh[BB * G3];                // h @ W_hh^T + b_hh
__device__ unsigned long long g_slots[BB];     // packed argmax slots
// fp16 2-level split weights, MMA B-fragment order:
// uint4 {w1b0, w1b1, w2b0, w2b1} at [(g * nks + ks) * 32 + lane]
__device__ uint4 g_wf[(size_t)NG * NKS * 32];          // W_out
__device__ uint4 g_wfih[(size_t)NGG * (EE / 16) * 32]; // W_ih (nks=32)
__device__ uint4 g_wfhh[(size_t)NGG * (HH / 16) * 32]; // W_hh (nks=64)

// ---------------- HMMA helpers ------------------------------------------------
__device__ __forceinline__ uint32_t smem_u32(const void* p) {
    uint32_t a;
    asm("{ .reg .u64 t; cvta.to.shared.u64 t, %1; cvt.u32.u64 %0, t; }"
        : "=r"(a) : "l"(p));
    return a;
}
__device__ __forceinline__ void ldsm4(uint32_t* r, uint32_t addr) {
    asm volatile("ldmatrix.sync.aligned.m8n8.x4.shared.b16 {%0,%1,%2,%3}, [%4];"
                 : "=r"(r[0]), "=r"(r[1]), "=r"(r[2]), "=r"(r[3]) : "r"(addr));
}
__device__ __forceinline__ void mma16816(float* d, const uint32_t* a,
                                         uint32_t b0, uint32_t b1) {
    asm volatile(
        "mma.sync.aligned.m16n8k16.row.col.f32.f16.f16.f32 "
        "{%0,%1,%2,%3}, {%4,%5,%6,%7}, {%8,%9}, {%0,%1,%2,%3};"
        : "+f"(d[0]), "+f"(d[1]), "+f"(d[2]), "+f"(d[3])
        : "r"(a[0]), "r"(a[1]), "r"(a[2]), "r"(a[3]), "r"(b0), "r"(b1));
}
__device__ __forceinline__ uint32_t pack_lohi(unsigned short lo,
                                              unsigned short hi) {
    return (uint32_t)lo | ((uint32_t)hi << 16);
}
__device__ __forceinline__ void split2(float x, unsigned short& s1,
                                       unsigned short& s2) {
    __half h1 = __float2half_rn(x);
    float f1 = __half2float(h1);
    __half h2 = __float2half_rn(x - f1);
    s1 = __half_as_ushort(h1);
    s2 = __half_as_ushort(h2);
}
__device__ __forceinline__ void cp16(uint32_t dst, const void* src) {
    asm volatile("cp.async.cg.shared.global [%0], [%1], 16;"
                 :: "r"(dst), "l"(src) : "memory");
}

// ---------------- threefry2x32 (exact JAX schedule) --------------------------
__host__ __device__ static inline void tf2x32(unsigned k0, unsigned k1,
                                              unsigned x0, unsigned x1,
                                              unsigned* o0, unsigned* o1) {
    unsigned ks2 = k0 ^ k1 ^ 0x1BD11BDAu;
#define TF_RND(R) { x0 += x1; x1 = (x1 << (R)) | (x1 >> (32 - (R))); x1 ^= x0; }
    x0 += k0; x1 += k1;
    TF_RND(13) TF_RND(15) TF_RND(26) TF_RND(6)
    x0 += k1;  x1 += ks2 + 1u;
    TF_RND(17) TF_RND(29) TF_RND(16) TF_RND(24)
    x0 += ks2; x1 += k0 + 2u;
    TF_RND(13) TF_RND(15) TF_RND(26) TF_RND(6)
    x0 += k0;  x1 += k1 + 3u;
    TF_RND(17) TF_RND(29) TF_RND(16) TF_RND(24)
    x0 += k1;  x1 += ks2 + 4u;
    TF_RND(13) TF_RND(15) TF_RND(26) TF_RND(6)
    x0 += ks2; x1 += k0 + 5u;
#undef TF_RND
    *o0 = x0; *o1 = x1;
}

__device__ __forceinline__ unsigned jax_bits32(unsigned k0, unsigned k1,
                                               unsigned e) {
    unsigned o0, o1;
    tf2x32(k0, k1, 0u, e, &o0, &o1);
    return o0 ^ o1;
}

__device__ __forceinline__ float gumbel_from_bits(unsigned bits) {
    float u = __uint_as_float((bits >> 9) | 0x3f800000u) - 1.0f;
    u = u + 1.17549435082228750797e-38f;   // == max(tiny, u0) in fp32
    return -logf(-logf(u));
}

__device__ __forceinline__ unsigned orderf(float f) {
    unsigned u = __float_as_uint(f);
    return (u & 0x80000000u) ? ~u : (u | 0x80000000u);
}

__device__ __forceinline__ unsigned long long gpack(float val, int v) {
    return ((unsigned long long)orderf(val) << 32) |
           (0xFFFFFFFFu - (unsigned)v);
}

__device__ __forceinline__ int decode_sid(unsigned long long slot) {
    return (int)(0xFFFFFFFFu - (unsigned)(slot & 0xFFFFFFFFull));
}

// ---------------- fragment-order split precompute (any W, any K) -------------
__global__ __launch_bounds__(256) void wfrag_kernel(const float* __restrict__ W,
                                                    uint4* __restrict__ dst,
                                                    int K) {
    size_t i = (size_t)blockIdx.x * 256 + threadIdx.x;
    int nks = K >> 4;
    int l  = (int)(i & 31);
    int gs = (int)(i >> 5);
    int ks = gs % nks;
    int g  = gs / nks;
    int n = 8 * g + (l >> 2);
    int k = 16 * ks + 2 * (l & 3);
    const float* row = W + (size_t)n * K + k;
    float2 x0 = *(const float2*)(row);
    float2 x1 = *(const float2*)(row + 8);
    unsigned short a1, a2, b1, b2, c1, c2, d1, d2;
    split2(x0.x, a1, a2); split2(x0.y, b1, b2);
    split2(x1.x, c1, c2); split2(x1.y, d1, d2);
    uint4 p;
    p.x = pack_lohi(a1, b1);   // w1 b0
    p.y = pack_lohi(c1, d1);   // w1 b1
    p.z = pack_lohi(a2, b2);   // w2 b0
    p.w = pack_lohi(c2, d2);   // w2 b1
    dst[i] = p;
}

// ---------------- init: h0 = concat(init_hidden, att_embedding) --------------
__global__ void init_kernel(const float* __restrict__ init_hidden,
                            const float* __restrict__ att) {
    int i = blockIdx.x * blockDim.x + threadIdx.x;   // [0, B*H)
    int b = i / HH, u = i % HH;
    g_h[i] = (u < DINIT) ? init_hidden[b * DINIT + u]
                         : att[b * DATT + (u - DINIT)];
}

// ---------------- gates via HMMA (fragment-split, fused id record) -----------
__global__ __launch_bounds__(256, 2) void gates_hmma(
    const float* __restrict__ emb, const int* __restrict__ inputs,
    const float* __restrict__ bih, const float* __restrict__ bhh,
    float* __restrict__ ids_out, int t, int write_ids) {

    __shared__ __align__(16) unsigned short sH1[64 * WP];
    __shared__ __align__(16) unsigned short sH2[64 * WP];
    __shared__ const float* rowp[64];

    const int tid = threadIdx.x;
    const int wid = tid >> 5, lid = tid & 31;

    const bool gi_part = blockIdx.x < 24;
    const int nb   = gi_part ? blockIdx.x : blockIdx.x - 24;
    const int K    = gi_part ? EE : HH;
    const int nkc  = K / KCH;
    const int nks  = K >> 4;
    const uint4* wf = gi_part ? g_wfih : g_wfhh;
    const float* bias = gi_part ? bih : bhh;
    float* C = gi_part ? g_gi : g_gh;

    if (tid < 64) {
        int sid = (t == 0) ? inputs[tid] : decode_sid(g_slots[tid]);
        rowp[tid] = gi_part ? (emb + (size_t)sid * EE)
                            : (g_h + (size_t)tid * HH);
        if (gi_part && blockIdx.x == 0 && write_ids && t > 0)
            ids_out[(size_t)tid * TT + (t - 1)] = (float)sid;
    }
    __syncthreads();

    const int hrow = tid >> 2, hk = (tid & 3) << 3;
    const float* hptr = rowp[hrow] + hk;

    float4 hre[2];
#pragma unroll
    for (int j = 0; j < 2; ++j) hre[j] = *(const float4*)(hptr + 4 * j);

    const int m0 = (wid & 1) << 5;
    const int n0 = (wid >> 1) << 5;

    const int gw = nb * 16 + (n0 >> 3);
    const uint4* wfp = wf + ((size_t)gw * nks) * 32 + lid;

    float acc[2][4][4];
#pragma unroll
    for (int mm = 0; mm < 2; ++mm)
#pragma unroll
        for (int nn = 0; nn < 4; ++nn)
#pragma unroll
            for (int q = 0; q < 4; ++q) acc[mm][nn][q] = 0.0f;

    const uint32_t aH1 = smem_u32(sH1), aH2 = smem_u32(sH2);
    const int lj = lid >> 3, lr = lid & 7;

    uint4 bcur[4], bnxt[4];
#pragma unroll
    for (int nn = 0; nn < 4; ++nn) bcur[nn] = wfp[(size_t)nn * nks * 32];

    for (int c = 0; c < nkc; ++c) {
        {
            unsigned short s1[8], s2[8];
            const float* xs = (const float*)hre;
#pragma unroll
            for (int j = 0; j < 8; ++j) split2(xs[j], s1[j], s2[j]);
            uint32_t* d1 = (uint32_t*)&sH1[hrow * WP + hk];
            uint32_t* d2 = (uint32_t*)&sH2[hrow * WP + hk];
#pragma unroll
            for (int j = 0; j < 4; ++j) {
                d1[j] = pack_lohi(s1[2 * j], s1[2 * j + 1]);
                d2[j] = pack_lohi(s2[2 * j], s2[2 * j + 1]);
            }
        }
        __syncthreads();

        if (c + 1 < nkc) {
            const float* hn = hptr + (c + 1) * KCH;
#pragma unroll
            for (int j = 0; j < 2; ++j) hre[j] = *(const float4*)(hn + 4 * j);
        }

#pragma unroll
        for (int ks = 0; ks < 2; ++ks) {
            const int kb = ks << 4;
            const int ksi = c * 2 + ks;

            if (ksi + 1 < nks) {
#pragma unroll
                for (int nn = 0; nn < 4; ++nn)
                    bnxt[nn] = wfp[((size_t)nn * nks + (ksi + 1)) * 32];
            }

            uint32_t a1[2][4], a2[2][4];
#pragma unroll
            for (int mm = 0; mm < 2; ++mm) {
                int row = m0 + (mm << 4) + ((lj & 1) << 3) + lr;
                int col = kb + ((lj >> 1) << 3);
                uint32_t off = (uint32_t)(row * WP + col) * 2;
                ldsm4(a1[mm], aH1 + off);
                ldsm4(a2[mm], aH2 + off);
            }

#pragma unroll
            for (int mm = 0; mm < 2; ++mm)
#pragma unroll
                for (int nn = 0; nn < 4; ++nn) {
                    mma16816(acc[mm][nn], a1[mm], bcur[nn].x, bcur[nn].y);
                    mma16816(acc[mm][nn], a2[mm], bcur[nn].x, bcur[nn].y);
                    mma16816(acc[mm][nn], a1[mm], bcur[nn].z, bcur[nn].w);
                }
#pragma unroll
            for (int nn = 0; nn < 4; ++nn) bcur[nn] = bnxt[nn];
        }
        __syncthreads();
    }

#pragma unroll
    for (int nn = 0; nn < 4; ++nn) {
        int n = nb * 128 + n0 + (nn << 3) + ((lid & 3) << 1);
        float2 bias2 = *(const float2*)(bias + n);
#pragma unroll
        for (int mm = 0; mm < 2; ++mm) {
            int b0i = m0 + (mm << 4) + (lid >> 2);
            *(float2*)(C + (size_t)b0i * G3 + n) =
                make_float2(acc[mm][nn][0] + bias2.x, acc[mm][nn][1] + bias2.y);
            *(float2*)(C + (size_t)(b0i + 8) * G3 + n) =
                make_float2(acc[mm][nn][2] + bias2.x, acc[mm][nn][3] + bias2.y);
        }
    }
}

// ---------------- logits via HMMA + cp.async B pipeline + fused sampling -----
// dynamic smem: [0, SB_BYTES): B stages; then sH1, sH2.
__global__ __launch_bounds__(256, 2) void logits_hmma(
    const float* __restrict__ bout, float* __restrict__ out,
    unsigned k0, unsigned k1) {

    extern __shared__ __align__(16) char dsm[];
    uint4* sB = (uint4*)dsm;
    unsigned short* sH1 = (unsigned short*)(dsm + SB_BYTES);
    unsigned short* sH2 = (unsigned short*)(dsm + SB_BYTES + SH_BYTES);

    const int tid = threadIdx.x;
    const int wid = tid >> 5, lid = tid & 31;
    const int v0 = blockIdx.x * 128;
    const int gbase = blockIdx.x * 16;

    const uint32_t sBaddr = smem_u32(sB);
    const uint32_t aH1 = smem_u32(sH1), aH2 = smem_u32(sH2);

    // cp.async copy mapping: j-th copy of this thread
    // x = (tid>>5) + 8j: nn = x&3, ksl = (x>>2)&1, g = x>>3
    const int cp_lane = tid & 31;
    int cp_nn[4], cp_ksl[4], cp_g[4];
#pragma unroll
    for (int j = 0; j < 4; ++j) {
        int x = (tid >> 5) + 8 * j;
        cp_nn[j] = x & 3; cp_ksl[j] = (x >> 2) & 1; cp_g[j] = x >> 3;
    }

    // issue stage for chunk c into slot c & (NSTG-1)
#define ISSUE_STAGE(c)                                                        \
    {                                                                         \
        int _slot = (c) & (NSTG - 1);                                         \
        _Pragma("unroll")                                                     \
        for (int j = 0; j < 4; ++j) {                                         \
            const uint4* src = g_wf +                                         \
                ((size_t)(gbase + (cp_g[j] << 2) + cp_nn[j]) * NKS +          \
                 (2 * (c) + cp_ksl[j])) * 32 + cp_lane;                       \
            uint32_t dst = sBaddr +                                           \
                (uint32_t)((_slot * STG_U4 +                                  \
                 (((cp_g[j] << 1) + cp_ksl[j]) * 4 + cp_nn[j]) * 32 +         \
                 cp_lane) * 16);                                              \
            cp16(dst, src);                                                   \
        }                                                                     \
        asm volatile("cp.async.commit_group;" ::: "memory");                  \
    }

    // prologue: stages 0..2
    ISSUE_STAGE(0)
    ISSUE_STAGE(1)
    ISSUE_STAGE(2)

    const int hrow = tid >> 2, hk = (tid & 3) << 3;
    const float* hptr = g_h + (size_t)hrow * HH + hk;

    float4 hre[2];
#pragma unroll
    for (int j = 0; j < 2; ++j) hre[j] = *(const float4*)(hptr + 4 * j);

    const int m0 = (wid & 1) << 5;
    const int n0 = (wid >> 1) << 5;
    const int gq = wid >> 1;          // n-group 0..3

    float acc[2][4][4];
#pragma unroll
    for (int mm = 0; mm < 2; ++mm)
#pragma unroll
        for (int nn = 0; nn < 4; ++nn)
#pragma unroll
            for (int q = 0; q < 4; ++q) acc[mm][nn][q] = 0.0f;

    const int lj = lid >> 3, lr = lid & 7;

    for (int c = 0; c < NKC; ++c) {
        // B stage c ready (3 pending -> wait to <=2 completes oldest)
        asm volatile("cp.async.wait_group 2;" ::: "memory");

        // convert + store h chunk
        {
            unsigned short s1[8], s2[8];
            const float* xs = (const float*)hre;
#pragma unroll
            for (int j = 0; j < 8; ++j) split2(xs[j], s1[j], s2[j]);
            uint32_t* d1 = (uint32_t*)&sH1[hrow * WP + hk];
            uint32_t* d2 = (uint32_t*)&sH2[hrow * WP + hk];
#pragma unroll
            for (int j = 0; j < 4; ++j) {
                d1[j] = pack_lohi(s1[2 * j], s1[2 * j + 1]);
                d2[j] = pack_lohi(s2[2 * j], s2[2 * j + 1]);
            }
        }
        __syncthreads();

        // issue stage c+3 (into the slot consumed at iter c-1)
        if (c + 3 < NKC) ISSUE_STAGE(c + 3)

        // prefetch next h chunk
        if (c + 1 < NKC) {
            const float* hn = hptr + (c + 1) * KCH;
#pragma unroll
            for (int j = 0; j < 2; ++j) hre[j] = *(const float4*)(hn + 4 * j);
        }

        const uint4* stg = sB + (size_t)(c & (NSTG - 1)) * STG_U4;
#pragma unroll
        for (int ks = 0; ks < 2; ++ks) {
            const int kb = ks << 4;

            uint32_t a1[2][4], a2[2][4];
#pragma unroll
            for (int mm = 0; mm < 2; ++mm) {
                int row = m0 + (mm << 4) + ((lj & 1) << 3) + lr;
                int col = kb + ((lj >> 1) << 3);
                uint32_t off = (uint32_t)(row * WP + col) * 2;
                ldsm4(a1[mm], aH1 + off);
                ldsm4(a2[mm], aH2 + off);
            }

            const uint4* bp = stg + (((gq << 1) + ks) * 4) * 32 + lid;
#pragma unroll
            for (int nn = 0; nn < 4; ++nn) {
                uint4 bv = bp[nn * 32];
#pragma unroll
                for (int mm = 0; mm < 2; ++mm) {
                    mma16816(acc[mm][nn], a1[mm], bv.x, bv.y);
                    mma16816(acc[mm][nn], a2[mm], bv.x, bv.y);
                    mma16816(acc[mm][nn], a1[mm], bv.z, bv.w);
                }
            }
        }
        __syncthreads();   // all warps done with sH before next chunk's store
    }

    // ---- epilogue: add bias, write logits, fused gumbel partial argmax ----
    unsigned long long bst[2][2] = {{0ull, 0ull}, {0ull, 0ull}};
#pragma unroll
    for (int nn = 0; nn < 4; ++nn) {
        int v = v0 + n0 + (nn << 3) + ((lid & 3) << 1);
        float2 bias = *(const float2*)(bout + v);
#pragma unroll
        for (int mm = 0; mm < 2; ++mm) {
            int b0i = m0 + (mm << 4) + (lid >> 2);
            float v00 = acc[mm][nn][0] + bias.x;
            float v01 = acc[mm][nn][1] + bias.y;
            float v10 = acc[mm][nn][2] + bias.x;
            float v11 = acc[mm][nn][3] + bias.y;
            *(float2*)(out + (size_t)b0i * VV + v)       = make_float2(v00, v01);
            *(float2*)(out + (size_t)(b0i + 8) * VV + v) = make_float2(v10, v11);

            unsigned e0 = (unsigned)(b0i * VV + v);
            unsigned e1 = (unsigned)((b0i + 8) * VV + v);
            unsigned long long p;
            p = gpack(v00 + gumbel_from_bits(jax_bits32(k0, k1, e0)), v);
            if (p > bst[mm][0]) bst[mm][0] = p;
            p = gpack(v01 + gumbel_from_bits(jax_bits32(k0, k1, e0 + 1)), v + 1);
            if (p > bst[mm][0]) bst[mm][0] = p;
            p = gpack(v10 + gumbel_from_bits(jax_bits32(k0, k1, e1)), v);
            if (p > bst[mm][1]) bst[mm][1] = p;
            p = gpack(v11 + gumbel_from_bits(jax_bits32(k0, k1, e1 + 1)), v + 1);
            if (p > bst[mm][1]) bst[mm][1] = p;
        }
    }
#pragma unroll
    for (int mm = 0; mm < 2; ++mm)
#pragma unroll
        for (int r = 0; r < 2; ++r) {
            unsigned long long x = bst[mm][r];
            unsigned long long y = __shfl_xor_sync(0xFFFFFFFFu, x, 1);
            if (y > x) x = y;
            y = __shfl_xor_sync(0xFFFFFFFFu, x, 2);
            if (y > x) x = y;
            if ((lid & 3) == 0) {
                int row = m0 + (mm << 4) + (lid >> 2) + 8 * r;
                atomicMax(&g_slots[row], x);
            }
        }
#undef ISSUE_STAGE
}

// ---------------- GRU elementwise update + slot reset ------------------------
__global__ void hnew_kernel() {
    int i = blockIdx.x * blockDim.x + threadIdx.x;   // [0, B*H)
    int b = i / HH, u = i % HH;
    const float* gi = g_gi + (size_t)b * G3;
    const float* gh = g_gh + (size_t)b * G3;
    float ir = gi[u], iz = gi[HH + u], in_ = gi[2 * HH + u];
    float hr = gh[u], hz = gh[HH + u], hn  = gh[2 * HH + u];
    float r = 1.0f / (1.0f + expf(-(ir + hr)));
    float z = 1.0f / (1.0f + expf(-(iz + hz)));
    float n = tanhf(in_ + r * hn);
    float h = g_h[i];
    g_h[i] = (1.0f - z) * n + z * h;
    if (i < BB) g_slots[i] = 0ull;   // reset argmax slots before logits+sample
}

// ---------------- final ids record (last step) -------------------------------
__global__ void record_final(float* __restrict__ ids_out, int write_ids) {
    int b = threadIdx.x;
    if (b < BB && write_ids)
        ids_out[(size_t)b * TT + (TT - 1)] =
            (float)decode_sid(g_slots[b]);
}

// ---------------- launch -----------------------------------------------------
extern "C" void kernel_launch(void* const* d_in, const int* in_sizes, int n_in,
                              void* d_out, int out_size) {
    (void)in_sizes;
    int o = (n_in >= 11) ? 1 : 0;   // optional max_length scalar at slot 1
    const int*   inputs      = (const int*)  d_in[0];
    const float* init_hidden = (const float*)d_in[1 + o];
    const float* att         = (const float*)d_in[2 + o];
    const float* emb         = (const float*)d_in[3 + o];
    const float* W_ih        = (const float*)d_in[4 + o];
    const float* W_hh        = (const float*)d_in[5 + o];
    const float* b_ih        = (const float*)d_in[6 + o];
    const float* b_hh        = (const float*)d_in[7 + o];
    const float* W_out       = (const float*)d_in[8 + o];
    const float* b_out       = (const float*)d_in[9 + o];
    float* out = (float*)d_out;

    const long long TBV = (long long)TT * BB * VV;
    const int has_ids   = ((long long)out_size >= TBV + (long long)BB * TT) ? 1 : 0;
    float* ids_out = out + TBV;

    // allow 75.8KB dynamic smem for the logits pipeline (idempotent)
    cudaFuncSetAttribute(logits_hmma,
                         cudaFuncAttributeMaxDynamicSharedMemorySize, DYN_TOTAL);

    // per-step PRNG keys: partitionable (fold-like) split of key(42)
    unsigned keys[TT][2];
    for (int t = 0; t < TT; ++t) {
        unsigned a, b;
        tf2x32(0u, 42u, 0u, (unsigned)t, &a, &b);
        keys[t][0] = a; keys[t][1] = b;
    }

    // one-time fragment splits
    {
        uint4* wf_ptr;
        cudaGetSymbolAddress((void**)&wf_ptr, g_wf);
        wfrag_kernel<<<(NG * NKS * 32) / 256, 256>>>(W_out, wf_ptr, HH);
        cudaGetSymbolAddress((void**)&wf_ptr, g_wfih);
        wfrag_kernel<<<(NGG * (EE / 16) * 32) / 256, 256>>>(W_ih, wf_ptr, EE);
        cudaGetSymbolAddress((void**)&wf_ptr, g_wfhh);
        wfrag_kernel<<<(NGG * (HH / 16) * 32) / 256, 256>>>(W_hh, wf_ptr, HH);
    }
    init_kernel<<<(BB * HH) / 256, 256>>>(init_hidden, att);
    for (int t = 0; t < TT; ++t) {
        gates_hmma<<<48, 256>>>(emb, inputs, b_ih, b_hh, ids_out, t, has_ids);
        hnew_kernel<<<(BB * HH) / 256, 256>>>();
        logits_hmma<<<VV / 128, 256, DYN_TOTAL>>>(b_out,
                                                  out + (size_t)t * BB * VV,
                                                  keys[t][0], keys[t][1]);
    }
    record_final<<<1, 64>>>(ids_out, has_ids);
}